// round 7
// baseline (speedup 1.0000x reference)
#include <cuda_runtime.h>
#include <cuda_bf16.h>
#include <cstdint>

#define D_OUT_ 32768
#define D_IN_  1024

// Scratch (device globals: allocation-free rule)
static __device__ __nv_bfloat16 g_dw[(size_t)D_OUT_ * D_IN_];   // 64 MB bf16(DeltaW)
static __device__ __nv_bfloat16 g_sig[(size_t)D_IN_ * D_IN_];   // 2 MB bf16(Sigma)
static __device__ float  g_g[D_OUT_];                            // per-row g accum
static __device__ double g_acc[2];                               // 0: act, 1: binary reg

// ---------------- PTX helpers (baseline PTX only; no sm_103a features) -----
__device__ __forceinline__ uint32_t smem_u32(const void* p) {
    uint32_t a;
    asm("{ .reg .u64 t; cvta.to.shared.u64 t, %1; cvt.u32.u64 %0, t; }" : "=r"(a) : "l"(p));
    return a;
}
#define CPA16(dst, src) \
    asm volatile("cp.async.cg.shared.global [%0], [%1], 16;" :: "r"(dst), "l"(src))
#define CPCOMMIT() asm volatile("cp.async.commit_group;" ::: "memory")
#define CPWAIT(n)  asm volatile("cp.async.wait_group %0;" :: "n"(n) : "memory")

#define LDSM4(r0, r1, r2, r3, a) \
    asm volatile("ldmatrix.sync.aligned.m8n8.x4.shared.b16 {%0,%1,%2,%3}, [%4];" \
        : "=r"(r0), "=r"(r1), "=r"(r2), "=r"(r3) : "r"(a))

#define MMA16816(c0, c1, c2, c3, a0, a1, a2, a3, b0, b1) \
    asm volatile("mma.sync.aligned.m16n8k16.row.col.f32.bf16.bf16.f32 " \
        "{%0,%1,%2,%3}, {%4,%5,%6,%7}, {%8,%9}, {%0,%1,%2,%3};" \
        : "+f"(c0), "+f"(c1), "+f"(c2), "+f"(c3) \
        : "r"(a0), "r"(a1), "r"(a2), "r"(a3), "r"(b0), "r"(b1))

#define SWZ(o) ((o) ^ (((o) >> 3) & 0x70))

__device__ __forceinline__ float2 bf2f2(uint32_t v) {
    __nv_bfloat162 b;
    *reinterpret_cast<uint32_t*>(&b) = v;
    return __bfloat1622float2(b);
}
__device__ __forceinline__ float tanha(float x) {
    float y;
    asm("tanh.approx.f32 %0, %1;" : "=f"(y) : "f"(x));
    return y;
}

// ---------------- kernels --------------------------------------------------

__global__ void init_kernel() {
    int i = blockIdx.x * blockDim.x + threadIdx.x;
    if (i < D_OUT_) g_g[i] = 0.f;
    if (i < 2) g_acc[i] = 0.0;
}

// Th = clip((tanh(Theta)+1)*0.6-0.1, 0, 1); DW = W - s*(Q+Th) -> bf16
// binary-reg partial: sum(1 - (2Th-1)^2)
__global__ void prep_kernel(const float4* __restrict__ W, const float4* __restrict__ Q,
                            const float* __restrict__ s, const float4* __restrict__ T) {
    const int n4 = D_OUT_ * D_IN_ / 4;
    float br = 0.f;
    uint2* out = reinterpret_cast<uint2*>(g_dw);
    for (int i = blockIdx.x * blockDim.x + threadIdx.x; i < n4; i += gridDim.x * blockDim.x) {
        const float sv = s[i >> 8];
        const float4 w = W[i], q = Q[i], t = T[i];

        float th0 = __saturatef(fmaf(tanha(t.x), 0.6f, 0.5f));
        float th1 = __saturatef(fmaf(tanha(t.y), 0.6f, 0.5f));
        float th2 = __saturatef(fmaf(tanha(t.z), 0.6f, 0.5f));
        float th3 = __saturatef(fmaf(tanha(t.w), 0.6f, 0.5f));

        float dw0 = w.x - sv * (q.x + th0);
        float dw1 = w.y - sv * (q.y + th1);
        float dw2 = w.z - sv * (q.z + th2);
        float dw3 = w.w - sv * (q.w + th3);

        float x0 = 2.f * th0 - 1.f, x1 = 2.f * th1 - 1.f;
        float x2 = 2.f * th2 - 1.f, x3 = 2.f * th3 - 1.f;
        br += (1.f - x0 * x0) + (1.f - x1 * x1) + (1.f - x2 * x2) + (1.f - x3 * x3);

        __nv_bfloat162 p0, p1;
        p0.x = __float2bfloat16_rn(dw0); p0.y = __float2bfloat16_rn(dw1);
        p1.x = __float2bfloat16_rn(dw2); p1.y = __float2bfloat16_rn(dw3);
        uint2 u;
        u.x = *reinterpret_cast<uint32_t*>(&p0);
        u.y = *reinterpret_cast<uint32_t*>(&p1);
        out[i] = u;
    }
    #pragma unroll
    for (int o = 16; o; o >>= 1) br += __shfl_down_sync(0xFFFFFFFFu, br, o);
    __shared__ float red[8];
    if ((threadIdx.x & 31) == 0) red[threadIdx.x >> 5] = br;
    __syncthreads();
    if (threadIdx.x == 0) {
        float t = 0.f;
        #pragma unroll
        for (int j = 0; j < 8; j++) t += red[j];
        atomicAdd(&g_acc[1], (double)t);
    }
}

__global__ void sigconv_kernel(const float4* __restrict__ S) {
    const int n4 = D_IN_ * D_IN_ / 4;
    uint2* out = reinterpret_cast<uint2*>(g_sig);
    for (int i = blockIdx.x * blockDim.x + threadIdx.x; i < n4; i += gridDim.x * blockDim.x) {
        float4 v = S[i];
        __nv_bfloat162 p0, p1;
        p0.x = __float2bfloat16_rn(v.x); p0.y = __float2bfloat16_rn(v.y);
        p1.x = __float2bfloat16_rn(v.z); p1.y = __float2bfloat16_rn(v.w);
        uint2 u;
        u.x = *reinterpret_cast<uint32_t*>(&p0);
        u.y = *reinterpret_cast<uint32_t*>(&p1);
        out[i] = u;
    }
}

// Z = DW @ Sigma^T. CTA tile 128(M) x 256(N), K streamed 16x64, 3-stage cp.async.
// 8 warps as 2(M) x 4(N), warp tile 64x64 (acc[4][8][4]).
// Fused epilogue: act += Z.*DW ; g[row] += rowsum(Z.*W)
#define STAGE_BYTES 49152             // 16 KB A + 32 KB B per stage
#define SMEM_BYTES  147456            // 3 stages

__global__ void __launch_bounds__(256, 1) gemm_kernel(const float* __restrict__ Wf) {
    extern __shared__ char smem[];
    const uint32_t s0 = smem_u32(smem);

    const int tid = threadIdx.x;
    const int lane = tid & 31, w = tid >> 5;
    const int wm = w & 1, wn = w >> 1;          // 2 warps along M, 4 along N
    const int grp = lane >> 2, qd = lane & 3;

    const int m0 = blockIdx.x * 128;

    // cp.async coords: A tile 128r x 8c(16B) = 1024 slots (4/thread),
    //                  B tile 256r x 8c       = 2048 slots (8/thread)
    const int ldc = tid & 7;
    const int lr0 = tid >> 3;                   // + i*32 rows per step

    // ldmatrix bases
    const int arow = wm * 64 + (lane & 7) + ((lane >> 3) & 1) * 8;   // + mt*16
    const int akh  = (lane >> 4) & 1;
    const int bnrow = wn * 64 + (lane & 7) + ((lane >> 4) & 1) * 8;  // + nt*16
    const int bkh  = (lane >> 3) & 1;

    float act = 0.f;

    #pragma unroll 1
    for (int nc = 0; nc < 4; nc++) {
        const int n0 = nc * 256;
        float acc[4][8][4];
        #pragma unroll
        for (int mt = 0; mt < 4; mt++)
            #pragma unroll
            for (int nt = 0; nt < 8; nt++)
                #pragma unroll
                for (int j = 0; j < 4; j++) acc[mt][nt][j] = 0.f;

        const __nv_bfloat16* baseA = g_dw  + (size_t)m0 * D_IN_;
        const __nv_bfloat16* baseB = g_sig + (size_t)n0 * D_IN_;

        // prologue: stages 0, 1
        #pragma unroll
        for (int p = 0; p < 2; p++) {
            const uint32_t dA = s0 + p * STAGE_BYTES;
            const uint32_t dB = dA + 16384;
            const __nv_bfloat16* sa = baseA + p * 64;
            const __nv_bfloat16* sb = baseB + p * 64;
            #pragma unroll
            for (int i = 0; i < 4; i++) {
                int r = lr0 + i * 32;
                CPA16(dA + SWZ(r * 128 + ldc * 16), sa + r * D_IN_ + ldc * 8);
            }
            #pragma unroll
            for (int i = 0; i < 8; i++) {
                int r = lr0 + i * 32;
                CPA16(dB + SWZ(r * 128 + ldc * 16), sb + r * D_IN_ + ldc * 8);
            }
            CPCOMMIT();
        }

        #pragma unroll 1
        for (int kc = 0; kc < 16; kc++) {
            if (kc < 15) { CPWAIT(1); } else { CPWAIT(0); }
            __syncthreads();

            if (kc < 14) {
                const int st = (kc + 2) % 3;
                const uint32_t dA = s0 + st * STAGE_BYTES;
                const uint32_t dB = dA + 16384;
                const __nv_bfloat16* sa = baseA + (kc + 2) * 64;
                const __nv_bfloat16* sb = baseB + (kc + 2) * 64;
                #pragma unroll
                for (int i = 0; i < 4; i++) {
                    int r = lr0 + i * 32;
                    CPA16(dA + SWZ(r * 128 + ldc * 16), sa + r * D_IN_ + ldc * 8);
                }
                #pragma unroll
                for (int i = 0; i < 8; i++) {
                    int r = lr0 + i * 32;
                    CPA16(dB + SWZ(r * 128 + ldc * 16), sb + r * D_IN_ + ldc * 8);
                }
                CPCOMMIT();
            }

            const uint32_t bA = s0 + (kc % 3) * STAGE_BYTES;
            const uint32_t bB = bA + 16384;

            #pragma unroll
            for (int ks = 0; ks < 4; ks++) {
                uint32_t a[4][4], b[8][2];
                #pragma unroll
                for (int mt = 0; mt < 4; mt++) {
                    const int r = arow + mt * 16;
                    uint32_t addr = bA + r * 128 + (((ks * 2 + akh) ^ (r & 7)) * 16);
                    LDSM4(a[mt][0], a[mt][1], a[mt][2], a[mt][3], addr);
                }
                #pragma unroll
                for (int np = 0; np < 4; np++) {
                    const int n = bnrow + np * 16;
                    uint32_t addr = bB + n * 128 + (((ks * 2 + bkh) ^ (n & 7)) * 16);
                    LDSM4(b[2 * np][0], b[2 * np][1], b[2 * np + 1][0], b[2 * np + 1][1], addr);
                }
                #pragma unroll
                for (int mt = 0; mt < 4; mt++)
                    #pragma unroll
                    for (int nt = 0; nt < 8; nt++)
                        MMA16816(acc[mt][nt][0], acc[mt][nt][1], acc[mt][nt][2], acc[mt][nt][3],
                                 a[mt][0], a[mt][1], a[mt][2], a[mt][3],
                                 b[nt][0], b[nt][1]);
            }
        }

        // ---- fused epilogue for this 256-col chunk ----
        #pragma unroll
        for (int mt = 0; mt < 4; mt++) {
            #pragma unroll
            for (int half = 0; half < 2; half++) {
                const int row = m0 + wm * 64 + mt * 16 + grp + half * 8;
                const float*         wrow = Wf   + (size_t)row * D_IN_ + n0 + wn * 64;
                const __nv_bfloat16* drow = g_dw + (size_t)row * D_IN_ + n0 + wn * 64;
                float ga = 0.f;
                #pragma unroll
                for (int nt = 0; nt < 8; nt++) {
                    const int col = nt * 8 + qd * 2;
                    float z0 = acc[mt][nt][half * 2 + 0];
                    float z1 = acc[mt][nt][half * 2 + 1];
                    float2 dv = bf2f2(*(const uint32_t*)(drow + col));
                    float2 wv = *(const float2*)(wrow + col);
                    act = fmaf(z0, dv.x, act); act = fmaf(z1, dv.y, act);
                    ga  = fmaf(z0, wv.x, ga);  ga  = fmaf(z1, wv.y, ga);
                }
                ga += __shfl_xor_sync(0xFFFFFFFFu, ga, 1);
                ga += __shfl_xor_sync(0xFFFFFFFFu, ga, 2);
                if (qd == 0) atomicAdd(&g_g[row], ga);
            }
        }
        // protect next nc's prologue writes into stages 0/1
        __syncthreads();
    }

    // CTA reduce act -> double atomic
    #pragma unroll
    for (int o = 16; o; o >>= 1) act += __shfl_down_sync(0xFFFFFFFFu, act, o);
    __shared__ float reda[8];
    if (lane == 0) reda[w] = act;
    __syncthreads();
    if (tid == 0) {
        float t = 0.f;
        #pragma unroll
        for (int j = 0; j < 8; j++) t += reda[j];
        atomicAdd(&g_acc[0], (double)t);
    }
}

__global__ void fin_kernel(float* __restrict__ out) {
    const int tid = threadIdx.x;
    double sg = 0.0;
    for (int i = tid; i < D_OUT_; i += 256) {
        double v = (double)g_g[i];
        sg += v * v;
    }
    #pragma unroll
    for (int o = 16; o; o >>= 1) sg += __shfl_down_sync(0xFFFFFFFFu, sg, o);
    __shared__ double red[8];
    if ((tid & 31) == 0) red[tid >> 5] = sg;
    __syncthreads();
    if (tid == 0) {
        double t = 0.0;
        #pragma unroll
        for (int j = 0; j < 8; j++) t += red[j];
        // total = act + lamb_reg*br + lamb * 4 * sum(g^2)
        out[0] = (float)(g_acc[0] + 0.0002 * g_acc[1] + 0.05 * 4.0 * t);
    }
}

// ---------------- launch ---------------------------------------------------
extern "C" void kernel_launch(void* const* d_in, const int* in_sizes, int n_in,
                              void* d_out, int out_size) {
    (void)in_sizes; (void)n_in; (void)out_size;
    const float* W  = (const float*)d_in[0];
    const float* Sg = (const float*)d_in[1];
    const float* Q  = (const float*)d_in[2];
    const float* s  = (const float*)d_in[3];
    const float* T  = (const float*)d_in[4];

    static bool attr_set = false;
    if (!attr_set) {
        cudaFuncSetAttribute(gemm_kernel, cudaFuncAttributeMaxDynamicSharedMemorySize, SMEM_BYTES);
        attr_set = true;
    }

    init_kernel<<<64, 512>>>();
    prep_kernel<<<2048, 256>>>((const float4*)W, (const float4*)Q, s, (const float4*)T);
    sigconv_kernel<<<512, 256>>>((const float4*)Sg);
    gemm_kernel<<<256, 256, SMEM_BYTES>>>(W);
    fin_kernel<<<1, 256>>>((float*)d_out);
}

// round 8
// speedup vs baseline: 1.1526x; 1.1526x over previous
#include <cuda_runtime.h>
#include <cuda_bf16.h>
#include <cstdint>

#define D_OUT_ 32768
#define D_IN_  1024

// Scratch (device globals: allocation-free rule)
static __device__ __nv_bfloat16 g_dw[(size_t)D_OUT_ * D_IN_];   // 64 MB bf16(DeltaW)
static __device__ __nv_bfloat16 g_sig[(size_t)D_IN_ * D_IN_];   // 2 MB bf16(Sigma)
static __device__ float  g_g[D_OUT_];                            // per-row g accum
static __device__ double g_acc[2];                               // 0: act, 1: binary reg

// ---------------- PTX helpers (baseline PTX only; no sm_103a features) -----
__device__ __forceinline__ uint32_t smem_u32(const void* p) {
    uint32_t a;
    asm("{ .reg .u64 t; cvta.to.shared.u64 t, %1; cvt.u32.u64 %0, t; }" : "=r"(a) : "l"(p));
    return a;
}
#define CPA16(dst, src) \
    asm volatile("cp.async.cg.shared.global [%0], [%1], 16;" :: "r"(dst), "l"(src))
#define CPCOMMIT() asm volatile("cp.async.commit_group;" ::: "memory")
#define CPWAIT(n)  asm volatile("cp.async.wait_group %0;" :: "n"(n) : "memory")

#define LDSM4(r0, r1, r2, r3, a) \
    asm volatile("ldmatrix.sync.aligned.m8n8.x4.shared.b16 {%0,%1,%2,%3}, [%4];" \
        : "=r"(r0), "=r"(r1), "=r"(r2), "=r"(r3) : "r"(a))

#define MMA16816(c0, c1, c2, c3, a0, a1, a2, a3, b0, b1) \
    asm volatile("mma.sync.aligned.m16n8k16.row.col.f32.bf16.bf16.f32 " \
        "{%0,%1,%2,%3}, {%4,%5,%6,%7}, {%8,%9}, {%0,%1,%2,%3};" \
        : "+f"(c0), "+f"(c1), "+f"(c2), "+f"(c3) \
        : "r"(a0), "r"(a1), "r"(a2), "r"(a3), "r"(b0), "r"(b1))

#define SWZ(o) ((o) ^ (((o) >> 3) & 0x70))

__device__ __forceinline__ float2 bf2f2(uint32_t v) {
    __nv_bfloat162 b;
    *reinterpret_cast<uint32_t*>(&b) = v;
    return __bfloat1622float2(b);
}
__device__ __forceinline__ float tanha(float x) {
    float y;
    asm("tanh.approx.f32 %0, %1;" : "=f"(y) : "f"(x));
    return y;
}

// ---------------- kernels --------------------------------------------------

__global__ void init_kernel() {
    int i = blockIdx.x * blockDim.x + threadIdx.x;
    if (i < D_OUT_) g_g[i] = 0.f;
    if (i < 2) g_acc[i] = 0.0;
}

// Th = clip((tanh(Theta)+1)*0.6-0.1, 0, 1); DW = W - s*(Q+Th) -> bf16
// binary-reg partial: sum(1 - (2Th-1)^2)
__global__ void prep_kernel(const float4* __restrict__ W, const float4* __restrict__ Q,
                            const float* __restrict__ s, const float4* __restrict__ T) {
    const int n4 = D_OUT_ * D_IN_ / 4;
    float br = 0.f;
    uint2* out = reinterpret_cast<uint2*>(g_dw);
    for (int i = blockIdx.x * blockDim.x + threadIdx.x; i < n4; i += gridDim.x * blockDim.x) {
        const float sv = s[i >> 8];
        const float4 w = W[i], q = Q[i], t = T[i];

        float th0 = __saturatef(fmaf(tanha(t.x), 0.6f, 0.5f));
        float th1 = __saturatef(fmaf(tanha(t.y), 0.6f, 0.5f));
        float th2 = __saturatef(fmaf(tanha(t.z), 0.6f, 0.5f));
        float th3 = __saturatef(fmaf(tanha(t.w), 0.6f, 0.5f));

        float dw0 = w.x - sv * (q.x + th0);
        float dw1 = w.y - sv * (q.y + th1);
        float dw2 = w.z - sv * (q.z + th2);
        float dw3 = w.w - sv * (q.w + th3);

        float x0 = 2.f * th0 - 1.f, x1 = 2.f * th1 - 1.f;
        float x2 = 2.f * th2 - 1.f, x3 = 2.f * th3 - 1.f;
        br += (1.f - x0 * x0) + (1.f - x1 * x1) + (1.f - x2 * x2) + (1.f - x3 * x3);

        __nv_bfloat162 p0, p1;
        p0.x = __float2bfloat16_rn(dw0); p0.y = __float2bfloat16_rn(dw1);
        p1.x = __float2bfloat16_rn(dw2); p1.y = __float2bfloat16_rn(dw3);
        uint2 u;
        u.x = *reinterpret_cast<uint32_t*>(&p0);
        u.y = *reinterpret_cast<uint32_t*>(&p1);
        out[i] = u;
    }
    #pragma unroll
    for (int o = 16; o; o >>= 1) br += __shfl_down_sync(0xFFFFFFFFu, br, o);
    __shared__ float red[8];
    if ((threadIdx.x & 31) == 0) red[threadIdx.x >> 5] = br;
    __syncthreads();
    if (threadIdx.x == 0) {
        float t = 0.f;
        #pragma unroll
        for (int j = 0; j < 8; j++) t += red[j];
        atomicAdd(&g_acc[1], (double)t);
    }
}

__global__ void sigconv_kernel(const float4* __restrict__ S) {
    const int n4 = D_IN_ * D_IN_ / 4;
    uint2* out = reinterpret_cast<uint2*>(g_sig);
    for (int i = blockIdx.x * blockDim.x + threadIdx.x; i < n4; i += gridDim.x * blockDim.x) {
        float4 v = S[i];
        __nv_bfloat162 p0, p1;
        p0.x = __float2bfloat16_rn(v.x); p0.y = __float2bfloat16_rn(v.y);
        p1.x = __float2bfloat16_rn(v.z); p1.y = __float2bfloat16_rn(v.w);
        uint2 u;
        u.x = *reinterpret_cast<uint32_t*>(&p0);
        u.y = *reinterpret_cast<uint32_t*>(&p1);
        out[i] = u;
    }
}

// Persistent streaming GEMM: Z = DW @ Sigma^T.
// 2048 work units = 256 M-tiles x 8 N-chunks (unit tile 128x128, full K=1024).
// 296 persistent CTAs (2/SM), 6-7 units each (~1% imbalance).
// K-chunks stream through a 3-stage cp.async rotation that continues ACROSS
// unit boundaries, so epilogues overlap in-flight prefetches (no drains).
// 8 warps as 4(M) x 2(N), warp tile 32x64. Fused epilogue as before.
#define NCTAS 296
#define NUNITS 2048
#define STAGE_BYTES 32768             // 16 KB A + 16 KB B per stage
#define SMEM_BYTES  98304             // 3 stages

__global__ void __launch_bounds__(256, 2) gemm_kernel(const float* __restrict__ Wf) {
    extern __shared__ char smem[];
    const uint32_t s0 = smem_u32(smem);

    const int tid = threadIdx.x;
    const int lane = tid & 31, w = tid >> 5;
    const int wm = w & 3, wn = w >> 2;          // 4 warps along M, 2 along N
    const int grp = lane >> 2, qd = lane & 3;

    // --- work assignment: CTAs 0..271 get 7 units, 272..295 get 6 ---
    const int c = blockIdx.x;
    const int ucount = (c < 272) ? 7 : 6;
    const int ustart = (c < 272) ? 7 * c : 1904 + 6 * (c - 272);
    const int nch = ucount * 16;                // total K-chunks in my stream

    // cp.async coords (A and B tiles both 128 rows x 8 cols of 16B)
    const int ldc = tid & 7;
    const int lr0 = tid >> 3;                   // + i*32
    const uint32_t swo[4] = {
        (uint32_t)SWZ((lr0 +  0) * 128 + ldc * 16), (uint32_t)SWZ((lr0 + 32) * 128 + ldc * 16),
        (uint32_t)SWZ((lr0 + 64) * 128 + ldc * 16), (uint32_t)SWZ((lr0 + 96) * 128 + ldc * 16) };

    // ldmatrix bases
    const int arow = wm * 32 + (lane & 7) + ((lane >> 3) & 1) * 8;  // + mt*16
    const int akh  = (lane >> 4) & 1;
    const int asx  = (arow & 7);
    const int bnrow = wn * 64 + (lane & 7) + ((lane >> 4) & 1) * 8; // + nt*16
    const int bkh  = (lane >> 3) & 1;

    float act = 0.f;

    // chunk loader: chunk index -> (unit, kc) -> global srcs, stage (idx%3)
    auto load_chunk = [&](int ci) {
        const int u  = ustart + (ci >> 4);
        const int kc = ci & 15;
        const __nv_bfloat16* sa = g_dw  + (size_t)((u >> 3) << 7) * D_IN_ + kc * 64;
        const __nv_bfloat16* sb = g_sig + (size_t)((u & 7)  << 7) * D_IN_ + kc * 64;
        const uint32_t dA = s0 + (ci % 3) * STAGE_BYTES;
        const uint32_t dB = dA + 16384;
        #pragma unroll
        for (int i = 0; i < 4; i++) {
            const int r = lr0 + i * 32;
            CPA16(dA + swo[i], sa + r * D_IN_ + ldc * 8);
            CPA16(dB + swo[i], sb + r * D_IN_ + ldc * 8);
        }
        CPCOMMIT();
    };

    // prologue: chunks 0 and 1
    load_chunk(0);
    load_chunk(1);

    int ch = 0;
    #pragma unroll 1
    for (int j = 0; j < ucount; j++) {
        const int u  = ustart + j;
        const int m0 = (u >> 3) << 7;
        const int n0 = (u & 7)  << 7;

        float acc[2][8][4];
        #pragma unroll
        for (int mt = 0; mt < 2; mt++)
            #pragma unroll
            for (int nt = 0; nt < 8; nt++)
                #pragma unroll
                for (int jj = 0; jj < 4; jj++) acc[mt][nt][jj] = 0.f;

        #pragma unroll 1
        for (int kc = 0; kc < 16; kc++, ch++) {
            CPWAIT(1);
            __syncthreads();

            // keep the stream full: prefetch chunk ch+2 (commit an empty
            // group otherwise so pending-count bookkeeping stays uniform)
            if (ch + 2 < nch) load_chunk(ch + 2);
            else              CPCOMMIT();

            const uint32_t bA = s0 + (ch % 3) * STAGE_BYTES;
            const uint32_t bB = bA + 16384;

            #pragma unroll
            for (int ks = 0; ks < 4; ks++) {
                uint32_t a[2][4], b[8][2];
                #pragma unroll
                for (int mt = 0; mt < 2; mt++) {
                    uint32_t addr = bA + (arow + mt * 16) * 128 +
                                    (((ks * 2 + akh) ^ asx) * 16);
                    LDSM4(a[mt][0], a[mt][1], a[mt][2], a[mt][3], addr);
                }
                #pragma unroll
                for (int np = 0; np < 4; np++) {
                    const int n = bnrow + np * 16;
                    uint32_t addr = bB + n * 128 + (((ks * 2 + bkh) ^ (n & 7)) * 16);
                    LDSM4(b[2 * np][0], b[2 * np][1], b[2 * np + 1][0], b[2 * np + 1][1], addr);
                }
                #pragma unroll
                for (int mt = 0; mt < 2; mt++)
                    #pragma unroll
                    for (int nt = 0; nt < 8; nt++)
                        MMA16816(acc[mt][nt][0], acc[mt][nt][1], acc[mt][nt][2], acc[mt][nt][3],
                                 a[mt][0], a[mt][1], a[mt][2], a[mt][3],
                                 b[nt][0], b[nt][1]);
            }
        }

        // ---- fused epilogue for this unit (overlaps in-flight prefetches) ----
        #pragma unroll
        for (int mt = 0; mt < 2; mt++) {
            #pragma unroll
            for (int half = 0; half < 2; half++) {
                const int row = m0 + wm * 32 + mt * 16 + grp + half * 8;
                const float*         wrow = Wf   + (size_t)row * D_IN_ + n0 + wn * 64;
                const __nv_bfloat16* drow = g_dw + (size_t)row * D_IN_ + n0 + wn * 64;
                float ga = 0.f;
                #pragma unroll
                for (int nt = 0; nt < 8; nt++) {
                    const int col = nt * 8 + qd * 2;
                    float z0 = acc[mt][nt][half * 2 + 0];
                    float z1 = acc[mt][nt][half * 2 + 1];
                    float2 dv = bf2f2(*(const uint32_t*)(drow + col));
                    float2 wv = *(const float2*)(wrow + col);
                    act = fmaf(z0, dv.x, act); act = fmaf(z1, dv.y, act);
                    ga  = fmaf(z0, wv.x, ga);  ga  = fmaf(z1, wv.y, ga);
                }
                ga += __shfl_xor_sync(0xFFFFFFFFu, ga, 1);
                ga += __shfl_xor_sync(0xFFFFFFFFu, ga, 2);
                if (qd == 0) atomicAdd(&g_g[row], ga);
            }
        }
        // next iteration's first CPWAIT+__syncthreads orders stage reuse
    }

    // CTA reduce act -> double atomic
    #pragma unroll
    for (int o = 16; o; o >>= 1) act += __shfl_down_sync(0xFFFFFFFFu, act, o);
    __shared__ float reda[8];
    if (lane == 0) reda[w] = act;
    __syncthreads();
    if (tid == 0) {
        float t = 0.f;
        #pragma unroll
        for (int jj = 0; jj < 8; jj++) t += reda[jj];
        atomicAdd(&g_acc[0], (double)t);
    }
}

__global__ void fin_kernel(float* __restrict__ out) {
    const int tid = threadIdx.x;
    double sg = 0.0;
    for (int i = tid; i < D_OUT_; i += 256) {
        double v = (double)g_g[i];
        sg += v * v;
    }
    #pragma unroll
    for (int o = 16; o; o >>= 1) sg += __shfl_down_sync(0xFFFFFFFFu, sg, o);
    __shared__ double red[8];
    if ((tid & 31) == 0) red[tid >> 5] = sg;
    __syncthreads();
    if (tid == 0) {
        double t = 0.0;
        #pragma unroll
        for (int j = 0; j < 8; j++) t += red[j];
        // total = act + lamb_reg*br + lamb * 4 * sum(g^2)
        out[0] = (float)(g_acc[0] + 0.0002 * g_acc[1] + 0.05 * 4.0 * t);
    }
}

// ---------------- launch ---------------------------------------------------
extern "C" void kernel_launch(void* const* d_in, const int* in_sizes, int n_in,
                              void* d_out, int out_size) {
    (void)in_sizes; (void)n_in; (void)out_size;
    const float* W  = (const float*)d_in[0];
    const float* Sg = (const float*)d_in[1];
    const float* Q  = (const float*)d_in[2];
    const float* s  = (const float*)d_in[3];
    const float* T  = (const float*)d_in[4];

    static bool attr_set = false;
    if (!attr_set) {
        cudaFuncSetAttribute(gemm_kernel, cudaFuncAttributeMaxDynamicSharedMemorySize, SMEM_BYTES);
        attr_set = true;
    }

    init_kernel<<<64, 512>>>();
    prep_kernel<<<2048, 256>>>((const float4*)W, (const float4*)Q, s, (const float4*)T);
    sigconv_kernel<<<512, 256>>>((const float4*)Sg);
    gemm_kernel<<<NCTAS, 256, SMEM_BYTES>>>(W);
    fin_kernel<<<1, 256>>>((float*)d_out);
}